// round 15
// baseline (speedup 1.0000x reference)
#include <cuda_runtime.h>

#define NL 4
#define BATCH 16384
#define THREADS 256
#define EPB 16
#define NBLK (BATCH / EPB)       // 1024 blocks, 2 per SM
#define XS_S 68
#define XC_S 132
#define XH_S 36
#define PROJ_S 72
#define NCHUNK 16
#define EPSV 1e-5f

typedef unsigned long long ull;
typedef unsigned int u32;

__device__ __forceinline__ ull pk2(float lo, float hi) {
    ull r; asm("mov.b64 %0,{%1,%2};" : "=l"(r) : "f"(lo), "f"(hi)); return r;
}
__device__ __forceinline__ void upk2(ull v, float& lo, float& hi) {
    asm("mov.b64 {%0,%1},%2;" : "=f"(lo), "=f"(hi) : "l"(v));
}
__device__ __forceinline__ ull ffma2(ull a, ull b, ull c) {
    ull d; asm("fma.rn.f32x2 %0,%1,%2,%3;" : "=l"(d) : "l"(a), "l"(b), "l"(c)); return d;
}
__device__ __forceinline__ float warp_sum(float v) {
    v += __shfl_xor_sync(0xffffffffu, v, 16);
    v += __shfl_xor_sync(0xffffffffu, v, 8);
    v += __shfl_xor_sync(0xffffffffu, v, 4);
    v += __shfl_xor_sync(0xffffffffu, v, 2);
    v += __shfl_xor_sync(0xffffffffu, v, 1);
    return v;
}
__device__ __forceinline__ float half_sum(float v) {
    v += __shfl_xor_sync(0xffffffffu, v, 8);
    v += __shfl_xor_sync(0xffffffffu, v, 4);
    v += __shfl_xor_sync(0xffffffffu, v, 2);
    v += __shfl_xor_sync(0xffffffffu, v, 1);
    return v;
}
__device__ __forceinline__ void group_bar(int q) {
    asm volatile("bar.sync %0, 128;" :: "r"(q + 1) : "memory");
}
// silu via single-MUFU tanh: v*sigmoid(v) = 0.5v(1+tanh(v/2))
__device__ __forceinline__ float siluf(float v) {
    float t;
    asm("tanh.approx.f32 %0, %1;" : "=f"(t) : "f"(0.5f * v));
    return 0.5f * v * (1.0f + t);
}
__device__ __forceinline__ float softplusf(float v) {
    return fmaxf(v, 0.0f) + __logf(1.0f + __expf(-fabsf(v)));
}
__device__ __forceinline__ float fget(float4 v, int r) {
    return r == 0 ? v.x : r == 1 ? v.y : r == 2 ? v.z : v.w;
}
__device__ __forceinline__ u32 uget(uint4 v, int r) {
    return r == 0 ? v.x : r == 1 ? v.y : r == 2 ? v.z : v.w;
}
__device__ __forceinline__ void bfsplit(float2 p, u32& h, u32& l) {
    asm("cvt.rn.satfinite.bf16x2.f32 %0,%1,%2;" : "=r"(h) : "f"(p.y), "f"(p.x));
    float h0 = __uint_as_float(h << 16);
    float h1 = __uint_as_float(h & 0xffff0000u);
    asm("cvt.rn.satfinite.bf16x2.f32 %0,%1,%2;" : "=r"(l) : "f"(p.y - h1), "f"(p.x - h0));
}
__device__ __forceinline__ void mma_bf16(float* c, const u32* a, u32 b0, u32 b1) {
    asm("mma.sync.aligned.m16n8k16.row.col.f32.bf16.bf16.f32 "
        "{%0,%1,%2,%3},{%4,%5,%6,%7},{%8,%9},{%0,%1,%2,%3};"
        : "+f"(c[0]), "+f"(c[1]), "+f"(c[2]), "+f"(c[3])
        : "r"(a[0]), "r"(a[1]), "r"(a[2]), "r"(a[3]), "r"(b0), "r"(b1));
}

// ---------- per-layer weight blob: fragment-order packing (L2-resident) ----------
// ipwP: wide-m layout [ks(4)][w(8)][lane(32)][8 u32]; word j: nt=j>>1, e=j&1,
//       kp = ks*8+cc+4e, col = 32w + 8nt + g.
// opwP: [ks(8)][nc(4)][lane(32)][4 u32] (unchanged R14)
// xpjP: [ks(8)][nt(5)][lane(32)][2 u32] (unchanged R14)
struct __align__(16) LayerBlob {
    u32 ipwPh[4 * 8 * 32 * 8];
    u32 ipwPl[4 * 8 * 32 * 8];
    u32 opwPh[8 * 4 * 32 * 4];
    u32 opwPl[8 * 4 * 32 * 4];
    u32 xpjPh[8 * 5 * 32 * 2];
    u32 xpjPl[8 * 5 * 32 * 2];
    float dtw[4 * 128];
    float cw3[128];
    float cb[128];
    float dtb[128];
    float dskip[128];
    float lng[64];
    float lnb[64];
};

__device__ LayerBlob g_blob[NL];
__device__ float g_fold_part[18 * NCHUNK * 64];

#define FOLD_BLKS (18 * NCHUNK)
#define B0 (NL * 8192)
#define B1 (B0 + NL * 4096)
#define B2 (B1 + NL * 2560)
#define B3 (B2 + NL * 512)
#define B4 (B3 + NL * 128)
#define B5 (B4 + NL * 128)
#define B6 (B5 + NL * 128)
#define B7 (B6 + NL * 128)
#define B8 (B7 + NL * 64)
#define B9 (B8 + NL * 64)
#define BLOB_BLKS ((B9 + 255) / 256)

__global__ void __launch_bounds__(256)
prep_all(const float* __restrict__ w_nr, const float* __restrict__ b_nr,
         const float* __restrict__ w_r,  const float* __restrict__ b_r,
         const float* __restrict__ w_in_nr, const float* __restrict__ w_in_r,
         const float* __restrict__ ipw, const float* __restrict__ opw,
         const float* __restrict__ xpw, const float* __restrict__ dtw,
         const float* __restrict__ cw,  const float* __restrict__ cb,
         const float* __restrict__ dtb, const float* __restrict__ dskip,
         const float* __restrict__ lng, const float* __restrict__ lnb) {
    if (blockIdx.x < FOLD_BLKS) {
        __shared__ float red[4][64];
        const int j = blockIdx.x / NCHUNK;
        const int chunk = blockIdx.x - j * NCHUNK;
        const int o = threadIdx.x & 63;
        const int cg = threadIdx.x >> 6;
        const float* vec;
        const float* mat;
        if (j < 12)       { vec = w_nr + j * 1000;        mat = w_in_nr; }
        else if (j == 12) { vec = b_nr;                   mat = w_in_nr; }
        else if (j < 17)  { vec = w_r + (j - 13) * 1000;  mat = w_in_r;  }
        else              { vec = b_r;                    mat = w_in_r;  }
        const int cbase = chunk * 63;
        const int cend = (cbase + 63 < 1000) ? cbase + 63 : 1000;
        float a0 = 0.f, a1 = 0.f;
        for (int c = cbase + cg * 2; c < cend; c += 8) {
            a0 = fmaf(vec[c], mat[c * 64 + o], a0);
            if (c + 1 < cend)
                a1 = fmaf(vec[c + 1], mat[(c + 1) * 64 + o], a1);
        }
        red[cg][o] = a0 + a1;
        __syncthreads();
        if (cg == 0)
            g_fold_part[(j * NCHUNK + chunk) * 64 + o] =
                (red[0][o] + red[1][o]) + (red[2][o] + red[3][o]);
        return;
    }
    int idx = (blockIdx.x - FOLD_BLKS) * 256 + threadIdx.x;
    if (idx < B0) {
        // ipw wide-m fragment pack
        int l = idx >> 13, r = idx & 8191;
        int j = r & 7, lane = (r >> 3) & 31, t2 = r >> 8;   // t2 0..31
        int w8 = t2 & 7, ks = t2 >> 3;
        int nt = j >> 1, e = j & 1;
        int g = lane >> 2, cc = lane & 3;
        int kp = ks * 8 + cc + 4 * e;
        int col = w8 * 32 + nt * 8 + g;
        const float* src = ipw + l * 16384 + kp * 512 + col;
        u32 h, lo; bfsplit(make_float2(src[0], src[256]), h, lo);
        g_blob[l].ipwPh[r] = h;
        g_blob[l].ipwPl[r] = lo;
    } else if (idx < B1) {
        int j2 = idx - B0, l = j2 >> 12, r = j2 & 4095;
        int jw = r & 3, lane = (r >> 2) & 31, t2 = r >> 7;
        int nc = t2 & 3, ks = t2 >> 2;
        int g = lane >> 2, cc = lane & 3;
        int kp = ks * 8 + cc + ((jw >= 2) ? 4 : 0);
        int nt = jw & 1;
        int n = nc * 16 + nt * 8 + g;
        const float* src = opw + l * 8192 + kp * 128 + n;
        u32 h, lo; bfsplit(make_float2(src[0], src[64]), h, lo);
        g_blob[l].opwPh[r] = h;
        g_blob[l].opwPl[r] = lo;
    } else if (idx < B2) {
        int j2 = idx - B1, l = j2 / 2560, r = j2 - l * 2560;
        int e = r & 1, lane = (r >> 1) & 31, t2 = r >> 6;
        int nt = t2 % 5, ks = t2 / 5;
        int g = lane >> 2, cc = lane & 3;
        int kp = ks * 8 + cc + (e ? 4 : 0);
        int n = nt * 8 + g;
        const float* src = xpw + l * 4608 + (2 * kp) * 36 + n;
        u32 h, lo; bfsplit(make_float2(src[0], src[36]), h, lo);
        g_blob[l].xpjPh[r] = h;
        g_blob[l].xpjPl[r] = lo;
    } else if (idx < B3) {
        int j = idx - B2, l = j >> 9, r = j & 511;
        g_blob[l].dtw[r] = dtw[l * 512 + r];
    } else if (idx < B4) {
        int j = idx - B3, l = j >> 7, r = j & 127;
        g_blob[l].cw3[r] = cw[(l * 128 + r) * 4 + 3];
    } else if (idx < B5) {
        int j = idx - B4, l = j >> 7, r = j & 127;
        g_blob[l].cb[r] = cb[l * 128 + r];
    } else if (idx < B6) {
        int j = idx - B5, l = j >> 7, r = j & 127;
        g_blob[l].dtb[r] = dtb[l * 128 + r];
    } else if (idx < B7) {
        int j = idx - B6, l = j >> 7, r = j & 127;
        g_blob[l].dskip[r] = dskip[l * 128 + r];
    } else if (idx < B8) {
        int j = idx - B7, l = j >> 6, r = j & 63;
        g_blob[l].lng[r] = lng[l * 64 + r];
    } else if (idx < B9) {
        int j = idx - B8, l = j >> 6, r = j & 63;
        g_blob[l].lnb[r] = lnb[l * 64 + r];
    }
}

// ---------------- shared memory (51,712 B; 2 blocks/SM) ----------------
struct __align__(16) Smem {
    u32 xsh[32 * XH_S];       // split residual hi; proj scratch between A and D
    u32 xsl[32 * XH_S];
    float xs[32 * XS_S];      // residual fp32
    float xc[32 * XC_S];      // split xc/y (hi cols 0..63, lo 64..127)
    float sz[32 * XC_S];      // silu(z), then O
};

__global__ void __launch_bounds__(THREADS, 2)
mamba_main(const float* __restrict__ xin,
           const float* __restrict__ b_in_nr, const float* __restrict__ b_in_r,
           const float* __restrict__ hw1, const float* __restrict__ hb1,
           const float* __restrict__ hw2, const float* __restrict__ hb2,
           float* __restrict__ out) {
    extern __shared__ __align__(16) char smem_raw[];
    Smem& s = *reinterpret_cast<Smem*>(smem_raw);

    const int t = threadIdx.x;
    const int w = t >> 5;          // 0..7
    const int lane = t & 31;
    const int q = w & 1;           // parity group for stages B/C/D
    const int nc = w >> 1;
    const int g = lane >> 2;
    const int cc = lane & 3;
    const int rb4 = 16 * q + 4 * nc;
    float* proj = (float*)s.xsh;

    // ---- fold-reduce into SMEM (union'd into xc region) ----
    float* Wnr_s = s.xc;
    float* Wr_s  = s.xc + 768;
    float* bnr_s = s.xc + 1024;
    float* br_s  = s.xc + 1088;
    for (int i = t; i < 1152; i += THREADS) {
        int j = i >> 6, o = i & 63;
        const float* p = g_fold_part + (j * NCHUNK) * 64 + o;
        float a = 0.0f;
#pragma unroll
        for (int k = 0; k < NCHUNK; k++) a += p[k * 64];
        if (j < 12)       Wnr_s[j * 64 + o] = a;
        else if (j == 12) bnr_s[o] = a + b_in_nr[o];
        else if (j < 17)  Wr_s[(j - 13) * 64 + o] = a;
        else              br_s[o] = a + b_in_r[o];
    }
    __syncthreads();

    // ---- x0 = feat @ W_eff + b_eff : warp w -> rows 4w..4w+3 ----
    {
        const int e0 = blockIdx.x * EPB + 2 * w;
        float fe[2][16];
#pragma unroll
        for (int e = 0; e < 2; e++) {
            const float4* xp = (const float4*)(xin + (size_t)(e0 + e) * 16);
#pragma unroll
            for (int qq = 0; qq < 4; qq++) {
                float4 v = xp[qq];
                fe[e][4 * qq + 0] = v.x; fe[e][4 * qq + 1] = v.y;
                fe[e][4 * qq + 2] = v.z; fe[e][4 * qq + 3] = v.w;
            }
        }
        float2 bn = *(const float2*)&bnr_s[2 * lane];
        float2 bb = *(const float2*)&br_s[2 * lane];
        ull a0 = pk2(bn.x, bn.y), a2 = a0;
        ull a1 = pk2(bb.x, bb.y), a3 = a1;
#pragma unroll
        for (int f = 0; f < 12; f++) {
            ull wp = *(const ull*)&Wnr_s[f * 64 + 2 * lane];
            a0 = ffma2(wp, pk2(fe[0][f], fe[0][f]), a0);
            a2 = ffma2(wp, pk2(fe[1][f], fe[1][f]), a2);
        }
#pragma unroll
        for (int f = 0; f < 4; f++) {
            ull wp = *(const ull*)&Wr_s[f * 64 + 2 * lane];
            a1 = ffma2(wp, pk2(fe[0][12 + f], fe[0][12 + f]), a1);
            a3 = ffma2(wp, pk2(fe[1][12 + f], fe[1][12 + f]), a3);
        }
        ull accs[4] = {a0, a1, a2, a3};
#pragma unroll
        for (int j = 0; j < 4; j++) {
            float v0, v1; upk2(accs[j], v0, v1);
            int row = 4 * w + j;
            *(float2*)&s.xs[row * XS_S + 2 * lane] = make_float2(v0, v1);
            u32 h, lo; bfsplit(make_float2(v0, v1), h, lo);
            s.xsh[row * XH_S + lane] = h;
            s.xsl[row * XH_S + lane] = lo;
        }
    }

    // ================= layer loop (weights served from L2) =================
#pragma unroll 1
    for (int l = 0; l < NL; l++) {
        const LayerBlob* __restrict__ gb = &g_blob[l];
        __syncthreads();

        // ======== stage A (wide-m): warp w -> 32 cols, BOTH m-tiles ========
        {
            float acc[2][4][4];
#pragma unroll
            for (int mt = 0; mt < 2; mt++)
#pragma unroll
                for (int nt = 0; nt < 4; nt++)
#pragma unroll
                    for (int i = 0; i < 4; i++) acc[mt][nt][i] = 0.0f;
#pragma unroll
            for (int ks = 0; ks < 4; ks++) {
                const int kp = ks * 8 + cc;
                const uint4* bh = (const uint4*)&gb->ipwPh[(((ks * 8 + w) * 32) + lane) * 8];
                const uint4* bl = (const uint4*)&gb->ipwPl[(((ks * 8 + w) * 32) + lane) * 8];
                uint4 BH0 = __ldg(bh), BH1 = __ldg(bh + 1);
                uint4 BL0 = __ldg(bl), BL1 = __ldg(bl + 1);
#pragma unroll
                for (int mt = 0; mt < 2; mt++) {
                    const int r0 = 16 * mt + g, r8 = r0 + 8;
                    u32 ah[4], al[4];
                    ah[0] = s.xsh[r0 * XH_S + kp];     ah[1] = s.xsh[r8 * XH_S + kp];
                    ah[2] = s.xsh[r0 * XH_S + kp + 4]; ah[3] = s.xsh[r8 * XH_S + kp + 4];
                    al[0] = s.xsl[r0 * XH_S + kp];     al[1] = s.xsl[r8 * XH_S + kp];
                    al[2] = s.xsl[r0 * XH_S + kp + 4]; al[3] = s.xsl[r8 * XH_S + kp + 4];
                    mma_bf16(acc[mt][0], ah, BH0.x, BH0.y);
                    mma_bf16(acc[mt][0], al, BH0.x, BH0.y);
                    mma_bf16(acc[mt][0], ah, BL0.x, BL0.y);
                    mma_bf16(acc[mt][1], ah, BH0.z, BH0.w);
                    mma_bf16(acc[mt][1], al, BH0.z, BH0.w);
                    mma_bf16(acc[mt][1], ah, BL0.z, BL0.w);
                    mma_bf16(acc[mt][2], ah, BH1.x, BH1.y);
                    mma_bf16(acc[mt][2], al, BH1.x, BH1.y);
                    mma_bf16(acc[mt][2], ah, BL1.x, BL1.y);
                    mma_bf16(acc[mt][3], ah, BH1.z, BH1.w);
                    mma_bf16(acc[mt][3], al, BH1.z, BH1.w);
                    mma_bf16(acc[mt][3], ah, BL1.z, BL1.w);
                }
            }
            if (w < 4) {        // xc cols 32w..32w+31: conv tap + silu, stored split
#pragma unroll
                for (int mt = 0; mt < 2; mt++) {
                    const int r0 = 16 * mt + g, r8 = r0 + 8;
                    u32* xr0 = (u32*)&s.xc[r0 * XC_S];
                    u32* xr8 = (u32*)&s.xc[r8 * XC_S];
#pragma unroll
                    for (int nt = 0; nt < 4; nt++) {
                        int col = 32 * w + 8 * nt + 2 * cc;
                        int p = col >> 1;
                        float2 cwv = *(const float2*)&gb->cw3[col];
                        float2 cbv = *(const float2*)&gb->cb[col];
                        float2 v0 = make_float2(siluf(fmaf(acc[mt][nt][0], cwv.x, cbv.x)),
                                                siluf(fmaf(acc[mt][nt][1], cwv.y, cbv.y)));
                        float2 v8 = make_float2(siluf(fmaf(acc[mt][nt][2], cwv.x, cbv.x)),
                                                siluf(fmaf(acc[mt][nt][3], cwv.y, cbv.y)));
                        u32 h, lo;
                        bfsplit(v0, h, lo); xr0[p] = h; xr0[64 + p] = lo;
                        bfsplit(v8, h, lo); xr8[p] = h; xr8[64 + p] = lo;
                    }
                }
            } else {            // z cols 32(w-4)..: silu, fp32
                const int wz = w - 4;
#pragma unroll
                for (int mt = 0; mt < 2; mt++) {
                    const int r0 = 16 * mt + g, r8 = r0 + 8;
#pragma unroll
                    for (int nt = 0; nt < 4; nt++) {
                        int col = 32 * wz + 8 * nt + 2 * cc;
                        *(float2*)&s.sz[r0 * XC_S + col] =
                            make_float2(siluf(acc[mt][nt][0]), siluf(acc[mt][nt][1]));
                        *(float2*)&s.sz[r8 * XC_S + col] =
                            make_float2(siluf(acc[mt][nt][2]), siluf(acc[mt][nt][3]));
                    }
                }
            }
        }
        __syncthreads();   // xsh/xsl reads done block-wide before proj overwrites

        // ======== proj GEMM: n-tiles 2/1/1/1 per (q,nc); B via LDG.64 ========
        {
            const int ntb = (nc == 0) ? 0 : nc + 1;
            const int nte = nc + 2;
            const int row0 = 16 * q + g, row8 = row0 + 8;
            const u32* yh0 = (const u32*)&s.xc[row0 * XC_S];
            const u32* yh8 = (const u32*)&s.xc[row8 * XC_S];
            float acc[2][4];
#pragma unroll
            for (int nt = 0; nt < 2; nt++)
#pragma unroll
                for (int i = 0; i < 4; i++) acc[nt][i] = 0.0f;
#pragma unroll
            for (int ks = 0; ks < 8; ks++) {
                const int kp = ks * 8 + cc;
                u32 ah[4], al[4];
                ah[0] = yh0[kp];          ah[1] = yh8[kp];
                ah[2] = yh0[kp + 4];      ah[3] = yh8[kp + 4];
                al[0] = yh0[64 + kp];     al[1] = yh8[64 + kp];
                al[2] = yh0[64 + kp + 4]; al[3] = yh8[64 + kp + 4];
                for (int nt = ntb; nt < nte; nt++) {
                    int a = nt - ntb;
                    ull hv = __ldg((const ull*)&gb->xpjPh[((ks * 5 + nt) * 32 + lane) * 2]);
                    ull lv = __ldg((const ull*)&gb->xpjPl[((ks * 5 + nt) * 32 + lane) * 2]);
                    u32 bh0 = (u32)hv, bh1 = (u32)(hv >> 32);
                    u32 bl0 = (u32)lv, bl1 = (u32)(lv >> 32);
                    mma_bf16(acc[a], ah, bh0, bh1);
                    mma_bf16(acc[a], ah, bl0, bl1);
                    mma_bf16(acc[a], al, bh0, bh1);
                }
            }
            for (int nt = ntb; nt < nte; nt++) {
                int a = nt - ntb;
                int col = nt * 8 + 2 * cc;
                *(float2*)&proj[row0 * PROJ_S + col] = make_float2(acc[a][0], acc[a][1]);
                *(float2*)&proj[row8 * PROJ_S + col] = make_float2(acc[a][2], acc[a][3]);
            }
        }
        group_bar(q);

        // ======== stage B: dt/BC/y for rows rb4..rb4+3 ========
        {
            float4 pj[4];
#pragma unroll
            for (int j = 0; j < 4; j++)
                pj[j] = *(const float4*)&proj[(rb4 + j) * PROJ_S];
            float bc[4];
            {
                const int j2 = lane >> 4, sidx = lane & 15;
#pragma unroll
                for (int a = 0; a < 2; a++) {
                    const float* pr = &proj[(rb4 + 2 * a + j2) * PROJ_S];
                    float v = pr[4 + sidx] * pr[20 + sidx];
                    v = half_sum(v);
                    bc[2 * a + 0] = __shfl_sync(0xffffffffu, v, 0);
                    bc[2 * a + 1] = __shfl_sync(0xffffffffu, v, 16);
                }
            }
            float dts[4][4];
            {
                float4 dtbv = __ldg((const float4*)&gb->dtb[4 * lane]);
#pragma unroll
                for (int j = 0; j < 4; j++) {
                    dts[j][0] = dtbv.x; dts[j][1] = dtbv.y;
                    dts[j][2] = dtbv.z; dts[j][3] = dtbv.w;
                }
#pragma unroll
                for (int r = 0; r < 4; r++) {
                    float4 dwv = __ldg((const float4*)&gb->dtw[r * 128 + 4 * lane]);
#pragma unroll
                    for (int j = 0; j < 4; j++) {
                        float prj = fget(pj[j], r);
                        dts[j][0] = fmaf(prj, dwv.x, dts[j][0]);
                        dts[j][1] = fmaf(prj, dwv.y, dts[j][1]);
                        dts[j][2] = fmaf(prj, dwv.z, dts[j][2]);
                        dts[j][3] = fmaf(prj, dwv.w, dts[j][3]);
                    }
                }
#pragma unroll
                for (int j = 0; j < 4; j++) {
                    dts[j][0] = softplusf(dts[j][0]); dts[j][1] = softplusf(dts[j][1]);
                    dts[j][2] = softplusf(dts[j][2]); dts[j][3] = softplusf(dts[j][3]);
                }
            }
            {
                float4 dskv = __ldg((const float4*)&gb->dskip[4 * lane]);
#pragma unroll
                for (int j = 0; j < 4; j++) {
                    u32* xr = (u32*)&s.xc[(rb4 + j) * XC_S];
                    uint2 hh = *(const uint2*)&xr[2 * lane];
                    uint2 ll = *(const uint2*)&xr[64 + 2 * lane];
                    float xc0 = __uint_as_float(hh.x << 16) + __uint_as_float(ll.x << 16);
                    float xc1 = __uint_as_float(hh.x & 0xffff0000u) + __uint_as_float(ll.x & 0xffff0000u);
                    float xc2 = __uint_as_float(hh.y << 16) + __uint_as_float(ll.y << 16);
                    float xc3 = __uint_as_float(hh.y & 0xffff0000u) + __uint_as_float(ll.y & 0xffff0000u);
                    float4 szv = *(const float4*)&s.sz[(rb4 + j) * XC_S + 4 * lane];
                    float4 yv;
                    yv.x = xc0 * fmaf(dts[j][0], bc[j], dskv.x) * szv.x;
                    yv.y = xc1 * fmaf(dts[j][1], bc[j], dskv.y) * szv.y;
                    yv.z = xc2 * fmaf(dts[j][2], bc[j], dskv.z) * szv.z;
                    yv.w = xc3 * fmaf(dts[j][3], bc[j], dskv.w) * szv.w;
                    u32 h0, l0, h1, l1;
                    bfsplit(make_float2(yv.x, yv.y), h0, l0);
                    bfsplit(make_float2(yv.z, yv.w), h1, l1);
                    *(uint2*)&xr[2 * lane]      = make_uint2(h0, h1);
                    *(uint2*)&xr[64 + 2 * lane] = make_uint2(l0, l1);
                }
            }
        }
        group_bar(q);

        // ======== stage C: out-proj GEMM; B via LDG.128 ========
        {
            const int row0 = 16 * q + g, row8 = row0 + 8;
            const u32* yh0 = (const u32*)&s.xc[row0 * XC_S];
            const u32* yh8 = (const u32*)&s.xc[row8 * XC_S];
            float acc[2][4];
#pragma unroll
            for (int nt = 0; nt < 2; nt++)
#pragma unroll
                for (int i = 0; i < 4; i++) acc[nt][i] = 0.0f;
#pragma unroll
            for (int ks = 0; ks < 8; ks++) {
                const int kp = ks * 8 + cc;
                u32 ah[4], al[4];
                ah[0] = yh0[kp];          ah[1] = yh8[kp];
                ah[2] = yh0[kp + 4];      ah[3] = yh8[kp + 4];
                al[0] = yh0[64 + kp];     al[1] = yh8[64 + kp];
                al[2] = yh0[64 + kp + 4]; al[3] = yh8[64 + kp + 4];
                uint4 UH = __ldg((const uint4*)&gb->opwPh[(((ks * 4 + nc) * 32) + lane) * 4]);
                uint4 UL = __ldg((const uint4*)&gb->opwPl[(((ks * 4 + nc) * 32) + lane) * 4]);
                mma_bf16(acc[0], ah, UH.x, UH.z);
                mma_bf16(acc[0], ah, UL.x, UL.z);
                mma_bf16(acc[0], al, UH.x, UH.z);
                mma_bf16(acc[1], ah, UH.y, UH.w);
                mma_bf16(acc[1], ah, UL.y, UL.w);
                mma_bf16(acc[1], al, UH.y, UH.w);
            }
#pragma unroll
            for (int nt = 0; nt < 2; nt++) {
                int col = nc * 16 + nt * 8 + 2 * cc;
                *(float2*)&s.sz[row0 * XC_S + col] = make_float2(acc[nt][0], acc[nt][1]);
                *(float2*)&s.sz[row8 * XC_S + col] = make_float2(acc[nt][2], acc[nt][3]);
            }
        }
        __syncthreads();   // all proj reads done before stage D rewrites xsh/xsl

        // ======== stage D: layernorm(64) + residual; write fp32 + split ========
        {
            float2 gv = __ldg((const float2*)&gb->lng[2 * lane]);
            float2 bv = __ldg((const float2*)&gb->lnb[2 * lane]);
#pragma unroll
            for (int j = 0; j < 4; j++) {
                int row = rb4 + j;
                float2 ov = *(const float2*)&s.sz[row * XC_S + 2 * lane];
                float m  = warp_sum(ov.x + ov.y) * (1.0f / 64.0f);
                float m2 = warp_sum(ov.x * ov.x + ov.y * ov.y) * (1.0f / 64.0f);
                float rs = rsqrtf(m2 - m * m + EPSV);
                float2 xv = *(const float2*)&s.xs[row * XS_S + 2 * lane];
                xv.x += (ov.x - m) * rs * gv.x + bv.x;
                xv.y += (ov.y - m) * rs * gv.y + bv.y;
                *(float2*)&s.xs[row * XS_S + 2 * lane] = xv;
                u32 h, lo; bfsplit(xv, h, lo);
                s.xsh[row * XH_S + lane] = h;
                s.xsl[row * XH_S + lane] = lo;
            }
        }
    }

    // ================= head =================
    __syncthreads();
    {
        float* hs = s.xc;   // reuse as hw1[128][33]
        for (int i = t; i < 4096; i += THREADS) {
            int k = i >> 5, c = i & 31;
            hs[k * 33 + c] = hw1[i];
        }
        float* hb1s = s.sz;
        float* hw2s = s.sz + 64;
        if (t < 32) { hb1s[t] = hb1[t]; hw2s[t] = hw2[t]; }
        __syncthreads();

        float b2v = hb2[0];
#pragma unroll
        for (int j = 0; j < 2; j++) {
            int ra = 4 * w + 2 * j;
            float h = hb1s[lane];
            const float* xa = &s.xs[ra * XS_S];
            const float* xb = &s.xs[(ra + 1) * XS_S];
#pragma unroll 8
            for (int k = 0; k < 64; k++) h = fmaf(xa[k], hs[k * 33 + lane], h);
#pragma unroll 8
            for (int k = 0; k < 64; k++) h = fmaf(xb[k], hs[(64 + k) * 33 + lane], h);
            h = fmaxf(h, 0.0f);
            float v = warp_sum(h * hw2s[lane]);
            if (lane == 0) out[blockIdx.x * EPB + 2 * w + j] = v + b2v;
        }
    }
}

extern "C" void kernel_launch(void* const* d_in, const int* in_sizes, int n_in,
                              void* d_out, int out_size) {
    const float* x        = (const float*)d_in[0];
    const float* w_nr     = (const float*)d_in[1];
    const float* b_nr     = (const float*)d_in[2];
    const float* w_r      = (const float*)d_in[3];
    const float* b_r      = (const float*)d_in[4];
    const float* w_in_nr  = (const float*)d_in[5];
    const float* b_in_nr  = (const float*)d_in[6];
    const float* w_in_r   = (const float*)d_in[7];
    const float* b_in_r   = (const float*)d_in[8];
    const float* ipw      = (const float*)d_in[9];
    const float* cw       = (const float*)d_in[10];
    const float* cb       = (const float*)d_in[11];
    const float* xpw      = (const float*)d_in[12];
    const float* dtw      = (const float*)d_in[13];
    const float* dtb      = (const float*)d_in[14];
    /* alog d_in[15] dead at L=1 (scan h0=0) */
    const float* dskip    = (const float*)d_in[16];
    const float* opw      = (const float*)d_in[17];
    const float* lng      = (const float*)d_in[18];
    const float* lnb      = (const float*)d_in[19];
    const float* hw1      = (const float*)d_in[20];
    const float* hb1      = (const float*)d_in[21];
    const float* hw2      = (const float*)d_in[22];
    const float* hb2      = (const float*)d_in[23];

    size_t smem = sizeof(Smem);
    cudaFuncSetAttribute((const void*)mamba_main,
                         cudaFuncAttributeMaxDynamicSharedMemorySize, (int)smem);

    prep_all<<<FOLD_BLKS + BLOB_BLKS, 256>>>(w_nr, b_nr, w_r, b_r, w_in_nr, w_in_r,
                                             ipw, opw, xpw, dtw, cw, cb, dtb, dskip,
                                             lng, lnb);
    mamba_main<<<NBLK, THREADS, smem>>>(x, b_in_nr, b_in_r, hw1, hb1, hw2, hb2,
                                        (float*)d_out);
}

// round 16
// speedup vs baseline: 1.0661x; 1.0661x over previous
#include <cuda_runtime.h>

#define NL 4
#define BATCH 16384
#define THREADS 256
#define EPB 16
#define NBLK (BATCH / EPB)       // 1024 blocks, 2 per SM
#define XS_S 68
#define XC_S 132
#define XH_S 36
#define PROJ_S 72
#define NCHUNK 16
#define EPSV 1e-5f

typedef unsigned long long ull;
typedef unsigned int u32;

__device__ __forceinline__ ull pk2(float lo, float hi) {
    ull r; asm("mov.b64 %0,{%1,%2};" : "=l"(r) : "f"(lo), "f"(hi)); return r;
}
__device__ __forceinline__ void upk2(ull v, float& lo, float& hi) {
    asm("mov.b64 {%0,%1},%2;" : "=f"(lo), "=f"(hi) : "l"(v));
}
__device__ __forceinline__ ull ffma2(ull a, ull b, ull c) {
    ull d; asm("fma.rn.f32x2 %0,%1,%2,%3;" : "=l"(d) : "l"(a), "l"(b), "l"(c)); return d;
}
__device__ __forceinline__ float warp_sum(float v) {
    v += __shfl_xor_sync(0xffffffffu, v, 16);
    v += __shfl_xor_sync(0xffffffffu, v, 8);
    v += __shfl_xor_sync(0xffffffffu, v, 4);
    v += __shfl_xor_sync(0xffffffffu, v, 2);
    v += __shfl_xor_sync(0xffffffffu, v, 1);
    return v;
}
__device__ __forceinline__ float half_sum(float v) {
    v += __shfl_xor_sync(0xffffffffu, v, 8);
    v += __shfl_xor_sync(0xffffffffu, v, 4);
    v += __shfl_xor_sync(0xffffffffu, v, 2);
    v += __shfl_xor_sync(0xffffffffu, v, 1);
    return v;
}
__device__ __forceinline__ void group_bar(int q) {
    asm volatile("bar.sync %0, 128;" :: "r"(q + 1) : "memory");
}
// silu via single-MUFU tanh: v*sigmoid(v) = 0.5v(1+tanh(v/2))
__device__ __forceinline__ float siluf(float v) {
    float t;
    asm("tanh.approx.f32 %0, %1;" : "=f"(t) : "f"(0.5f * v));
    return 0.5f * v * (1.0f + t);
}
__device__ __forceinline__ float softplusf(float v) {
    return fmaxf(v, 0.0f) + __logf(1.0f + __expf(-fabsf(v)));
}
__device__ __forceinline__ float fget(float4 v, int r) {
    return r == 0 ? v.x : r == 1 ? v.y : r == 2 ? v.z : v.w;
}
__device__ __forceinline__ u32 uget(uint4 v, int r) {
    return r == 0 ? v.x : r == 1 ? v.y : r == 2 ? v.z : v.w;
}
__device__ __forceinline__ void bfsplit(float2 p, u32& h, u32& l) {
    asm("cvt.rn.satfinite.bf16x2.f32 %0,%1,%2;" : "=r"(h) : "f"(p.y), "f"(p.x));
    float h0 = __uint_as_float(h << 16);
    float h1 = __uint_as_float(h & 0xffff0000u);
    asm("cvt.rn.satfinite.bf16x2.f32 %0,%1,%2;" : "=r"(l) : "f"(p.y - h1), "f"(p.x - h0));
}
__device__ __forceinline__ void mma_bf16(float* c, const u32* a, u32 b0, u32 b1) {
    asm("mma.sync.aligned.m16n8k16.row.col.f32.bf16.bf16.f32 "
        "{%0,%1,%2,%3},{%4,%5,%6,%7},{%8,%9},{%0,%1,%2,%3};"
        : "+f"(c[0]), "+f"(c[1]), "+f"(c[2]), "+f"(c[3])
        : "r"(a[0]), "r"(a[1]), "r"(a[2]), "r"(a[3]), "r"(b0), "r"(b1));
}

// ---------- per-layer weight blob: fragment-order packing (L2-resident, R14) ----------
struct __align__(16) LayerBlob {
    u32 ipwPh[4 * 4 * 32 * 16];
    u32 ipwPl[4 * 4 * 32 * 16];
    u32 opwPh[8 * 4 * 32 * 4];
    u32 opwPl[8 * 4 * 32 * 4];
    u32 xpjPh[8 * 5 * 32 * 2];
    u32 xpjPl[8 * 5 * 32 * 2];
    float dtw[4 * 128];
    float cw3[128];
    float cb[128];
    float dtb[128];
    float dskip[128];
    float lng[64];
    float lnb[64];
};

__device__ LayerBlob g_blob[NL];
__device__ float g_fold_part[18 * NCHUNK * 64];

#define FOLD_BLKS (18 * NCHUNK)
#define B0 (NL * 8192)
#define B1 (B0 + NL * 4096)
#define B2 (B1 + NL * 2560)
#define B3 (B2 + NL * 512)
#define B4 (B3 + NL * 128)
#define B5 (B4 + NL * 128)
#define B6 (B5 + NL * 128)
#define B7 (B6 + NL * 128)
#define B8 (B7 + NL * 64)
#define B9 (B8 + NL * 64)
#define BLOB_BLKS ((B9 + 255) / 256)

__global__ void __launch_bounds__(256)
prep_all(const float* __restrict__ w_nr, const float* __restrict__ b_nr,
         const float* __restrict__ w_r,  const float* __restrict__ b_r,
         const float* __restrict__ w_in_nr, const float* __restrict__ w_in_r,
         const float* __restrict__ ipw, const float* __restrict__ opw,
         const float* __restrict__ xpw, const float* __restrict__ dtw,
         const float* __restrict__ cw,  const float* __restrict__ cb,
         const float* __restrict__ dtb, const float* __restrict__ dskip,
         const float* __restrict__ lng, const float* __restrict__ lnb) {
    if (blockIdx.x < FOLD_BLKS) {
        __shared__ float red[4][64];
        const int j = blockIdx.x / NCHUNK;
        const int chunk = blockIdx.x - j * NCHUNK;
        const int o = threadIdx.x & 63;
        const int cg = threadIdx.x >> 6;
        const float* vec;
        const float* mat;
        if (j < 12)       { vec = w_nr + j * 1000;        mat = w_in_nr; }
        else if (j == 12) { vec = b_nr;                   mat = w_in_nr; }
        else if (j < 17)  { vec = w_r + (j - 13) * 1000;  mat = w_in_r;  }
        else              { vec = b_r;                    mat = w_in_r;  }
        const int cbase = chunk * 63;
        const int cend = (cbase + 63 < 1000) ? cbase + 63 : 1000;
        float a0 = 0.f, a1 = 0.f;
        for (int c = cbase + cg * 2; c < cend; c += 8) {
            a0 = fmaf(vec[c], mat[c * 64 + o], a0);
            if (c + 1 < cend)
                a1 = fmaf(vec[c + 1], mat[(c + 1) * 64 + o], a1);
        }
        red[cg][o] = a0 + a1;
        __syncthreads();
        if (cg == 0)
            g_fold_part[(j * NCHUNK + chunk) * 64 + o] =
                (red[0][o] + red[1][o]) + (red[2][o] + red[3][o]);
        return;
    }
    int idx = (blockIdx.x - FOLD_BLKS) * 256 + threadIdx.x;
    if (idx < B0) {
        int l = idx >> 13, r = idx & 8191;
        int pos = r & 15, lane = (r >> 4) & 31, t2 = r >> 9;
        int nc = t2 & 3, ks = t2 >> 2;
        int sw = (lane >> 1) & 3;
        int c = (pos >> 2) ^ sw;
        int jw = pos & 3;
        int g = lane >> 2, cc = lane & 3;
        int kp = ks * 8 + cc + ((c >= 2) ? 4 : 0);
        int nt = (c & 1) * 4 + jw;
        int n = nc * 64 + nt * 8 + g;
        const float* src = ipw + l * 16384 + kp * 512 + n;
        u32 h, lo; bfsplit(make_float2(src[0], src[256]), h, lo);
        g_blob[l].ipwPh[r] = h;
        g_blob[l].ipwPl[r] = lo;
    } else if (idx < B1) {
        int j2 = idx - B0, l = j2 >> 12, r = j2 & 4095;
        int jw = r & 3, lane = (r >> 2) & 31, t2 = r >> 7;
        int nc = t2 & 3, ks = t2 >> 2;
        int g = lane >> 2, cc = lane & 3;
        int kp = ks * 8 + cc + ((jw >= 2) ? 4 : 0);
        int nt = jw & 1;
        int n = nc * 16 + nt * 8 + g;
        const float* src = opw + l * 8192 + kp * 128 + n;
        u32 h, lo; bfsplit(make_float2(src[0], src[64]), h, lo);
        g_blob[l].opwPh[r] = h;
        g_blob[l].opwPl[r] = lo;
    } else if (idx < B2) {
        int j2 = idx - B1, l = j2 / 2560, r = j2 - l * 2560;
        int e = r & 1, lane = (r >> 1) & 31, t2 = r >> 6;
        int nt = t2 % 5, ks = t2 / 5;
        int g = lane >> 2, cc = lane & 3;
        int kp = ks * 8 + cc + (e ? 4 : 0);
        int n = nt * 8 + g;
        const float* src = xpw + l * 4608 + (2 * kp) * 36 + n;
        u32 h, lo; bfsplit(make_float2(src[0], src[36]), h, lo);
        g_blob[l].xpjPh[r] = h;
        g_blob[l].xpjPl[r] = lo;
    } else if (idx < B3) {
        int j = idx - B2, l = j >> 9, r = j & 511;
        g_blob[l].dtw[r] = dtw[l * 512 + r];
    } else if (idx < B4) {
        int j = idx - B3, l = j >> 7, r = j & 127;
        g_blob[l].cw3[r] = cw[(l * 128 + r) * 4 + 3];
    } else if (idx < B5) {
        int j = idx - B4, l = j >> 7, r = j & 127;
        g_blob[l].cb[r] = cb[l * 128 + r];
    } else if (idx < B6) {
        int j = idx - B5, l = j >> 7, r = j & 127;
        g_blob[l].dtb[r] = dtb[l * 128 + r];
    } else if (idx < B7) {
        int j = idx - B6, l = j >> 7, r = j & 127;
        g_blob[l].dskip[r] = dskip[l * 128 + r];
    } else if (idx < B8) {
        int j = idx - B7, l = j >> 6, r = j & 63;
        g_blob[l].lng[r] = lng[l * 64 + r];
    } else if (idx < B9) {
        int j = idx - B8, l = j >> 6, r = j & 63;
        g_blob[l].lnb[r] = lnb[l * 64 + r];
    }
}

// ---------------- shared memory (51,712 B; 2 blocks/SM) ----------------
struct __align__(16) Smem {
    u32 xsh[32 * XH_S];
    u32 xsl[32 * XH_S];
    float xs[32 * XS_S];
    float xc[32 * XC_S];
    float sz[32 * XC_S];
};

__global__ void __launch_bounds__(THREADS, 2)
mamba_main(const float* __restrict__ xin,
           const float* __restrict__ b_in_nr, const float* __restrict__ b_in_r,
           const float* __restrict__ hw1, const float* __restrict__ hb1,
           const float* __restrict__ hw2, const float* __restrict__ hb2,
           float* __restrict__ out) {
    extern __shared__ __align__(16) char smem_raw[];
    Smem& s = *reinterpret_cast<Smem*>(smem_raw);

    const int t = threadIdx.x;
    const int w = t >> 5;          // 0..7
    const int lane = t & 31;
    const int q = w & 1;
    const int nc = w >> 1;
    const int g = lane >> 2;
    const int cc = lane & 3;
    const int sw = (lane >> 1) & 3;
    const int rb4 = 16 * q + 4 * nc;
    float* proj = (float*)s.xsh;

    // ---- fold-reduce into SMEM (union'd into xc region) ----
    float* Wnr_s = s.xc;
    float* Wr_s  = s.xc + 768;
    float* bnr_s = s.xc + 1024;
    float* br_s  = s.xc + 1088;
    for (int i = t; i < 1152; i += THREADS) {
        int j = i >> 6, o = i & 63;
        const float* p = g_fold_part + (j * NCHUNK) * 64 + o;
        float a = 0.0f;
#pragma unroll
        for (int k = 0; k < NCHUNK; k++) a += p[k * 64];
        if (j < 12)       Wnr_s[j * 64 + o] = a;
        else if (j == 12) bnr_s[o] = a + b_in_nr[o];
        else if (j < 17)  Wr_s[(j - 13) * 64 + o] = a;
        else              br_s[o] = a + b_in_r[o];
    }
    __syncthreads();

    // ---- x0 = feat @ W_eff + b_eff : warp w -> rows 4w..4w+3 ----
    {
        const int e0 = blockIdx.x * EPB + 2 * w;
        float fe[2][16];
#pragma unroll
        for (int e = 0; e < 2; e++) {
            const float4* xp = (const float4*)(xin + (size_t)(e0 + e) * 16);
#pragma unroll
            for (int qq = 0; qq < 4; qq++) {
                float4 v = xp[qq];
                fe[e][4 * qq + 0] = v.x; fe[e][4 * qq + 1] = v.y;
                fe[e][4 * qq + 2] = v.z; fe[e][4 * qq + 3] = v.w;
            }
        }
        float2 bn = *(const float2*)&bnr_s[2 * lane];
        float2 bb = *(const float2*)&br_s[2 * lane];
        ull a0 = pk2(bn.x, bn.y), a2 = a0;
        ull a1 = pk2(bb.x, bb.y), a3 = a1;
#pragma unroll
        for (int f = 0; f < 12; f++) {
            ull wp = *(const ull*)&Wnr_s[f * 64 + 2 * lane];
            a0 = ffma2(wp, pk2(fe[0][f], fe[0][f]), a0);
            a2 = ffma2(wp, pk2(fe[1][f], fe[1][f]), a2);
        }
#pragma unroll
        for (int f = 0; f < 4; f++) {
            ull wp = *(const ull*)&Wr_s[f * 64 + 2 * lane];
            a1 = ffma2(wp, pk2(fe[0][12 + f], fe[0][12 + f]), a1);
            a3 = ffma2(wp, pk2(fe[1][12 + f], fe[1][12 + f]), a3);
        }
        ull accs[4] = {a0, a1, a2, a3};
#pragma unroll
        for (int j = 0; j < 4; j++) {
            float v0, v1; upk2(accs[j], v0, v1);
            int row = 4 * w + j;
            *(float2*)&s.xs[row * XS_S + 2 * lane] = make_float2(v0, v1);
            u32 h, lo; bfsplit(make_float2(v0, v1), h, lo);
            s.xsh[row * XH_S + lane] = h;
            s.xsl[row * XH_S + lane] = lo;
        }
    }

    // ================= layer loop (weights served from L2) =================
#pragma unroll 1
    for (int l = 0; l < NL; l++) {
        const LayerBlob* __restrict__ gb = &g_blob[l];
        __syncthreads();

        // ======== stage A: xz GEMM; B frags via LDG.128 from L2 ========
        {
            const int row0 = 16 * q + g, row8 = row0 + 8;
            const u32* xh0 = &s.xsh[row0 * XH_S];
            const u32* xh8 = &s.xsh[row8 * XH_S];
            const u32* xl0 = &s.xsl[row0 * XH_S];
            const u32* xl8 = &s.xsl[row8 * XH_S];
            float acc[8][4];
#pragma unroll
            for (int nt = 0; nt < 8; nt++)
#pragma unroll
                for (int i = 0; i < 4; i++) acc[nt][i] = 0.0f;
#pragma unroll
            for (int ks = 0; ks < 4; ks++) {
                const int kp = ks * 8 + cc;
                u32 ah[4], al[4];
                ah[0] = xh0[kp];     ah[1] = xh8[kp];
                ah[2] = xh0[kp + 4]; ah[3] = xh8[kp + 4];
                al[0] = xl0[kp];     al[1] = xl8[kp];
                al[2] = xl0[kp + 4]; al[3] = xl8[kp + 4];
                const uint4* bp_h = (const uint4*)&gb->ipwPh[(((ks * 4 + nc) * 32) + lane) * 16];
                const uint4* bp_l = (const uint4*)&gb->ipwPl[(((ks * 4 + nc) * 32) + lane) * 16];
                uint4 H0 = __ldg(&bp_h[0 ^ sw]);
                uint4 H1 = __ldg(&bp_h[1 ^ sw]);
                uint4 H2 = __ldg(&bp_h[2 ^ sw]);
                uint4 H3 = __ldg(&bp_h[3 ^ sw]);
                uint4 L0 = __ldg(&bp_l[0 ^ sw]);
                uint4 L1 = __ldg(&bp_l[1 ^ sw]);
                uint4 L2 = __ldg(&bp_l[2 ^ sw]);
                uint4 L3 = __ldg(&bp_l[3 ^ sw]);
#pragma unroll
                for (int nt = 0; nt < 8; nt++) {
                    u32 b0 = nt < 4 ? uget(H0, nt) : uget(H1, nt - 4);
                    u32 b1 = nt < 4 ? uget(H2, nt) : uget(H3, nt - 4);
                    mma_bf16(acc[nt], ah, b0, b1);
                    mma_bf16(acc[nt], al, b0, b1);
                }
#pragma unroll
                for (int nt = 0; nt < 8; nt++) {
                    u32 b0 = nt < 4 ? uget(L0, nt) : uget(L1, nt - 4);
                    u32 b1 = nt < 4 ? uget(L2, nt) : uget(L3, nt - 4);
                    mma_bf16(acc[nt], ah, b0, b1);
                }
            }
            if (nc < 2) {        // xc half: conv tap + silu, stored split
                u32* xr0 = (u32*)&s.xc[row0 * XC_S];
                u32* xr8 = (u32*)&s.xc[row8 * XC_S];
#pragma unroll
                for (int nt = 0; nt < 8; nt++) {
                    int col = nc * 64 + nt * 8 + 2 * cc;
                    int p = col >> 1;
                    float2 cwv = *(const float2*)&gb->cw3[col];
                    float2 cbv = *(const float2*)&gb->cb[col];
                    float2 v0 = make_float2(siluf(fmaf(acc[nt][0], cwv.x, cbv.x)),
                                            siluf(fmaf(acc[nt][1], cwv.y, cbv.y)));
                    float2 v8 = make_float2(siluf(fmaf(acc[nt][2], cwv.x, cbv.x)),
                                            siluf(fmaf(acc[nt][3], cwv.y, cbv.y)));
                    u32 h, lo;
                    bfsplit(v0, h, lo); xr0[p] = h; xr0[64 + p] = lo;
                    bfsplit(v8, h, lo); xr8[p] = h; xr8[64 + p] = lo;
                }
            } else {             // z half: silu, fp32
#pragma unroll
                for (int nt = 0; nt < 8; nt++) {
                    int col = (nc - 2) * 64 + nt * 8 + 2 * cc;
                    *(float2*)&s.sz[row0 * XC_S + col] =
                        make_float2(siluf(acc[nt][0]), siluf(acc[nt][1]));
                    *(float2*)&s.sz[row8 * XC_S + col] =
                        make_float2(siluf(acc[nt][2]), siluf(acc[nt][3]));
                }
            }
        }
        __syncthreads();

        // ======== proj GEMM: n-tiles 2/1/1/1; B via LDG.64 ========
        {
            const int ntb = (nc == 0) ? 0 : nc + 1;
            const int nte = nc + 2;
            const int row0 = 16 * q + g, row8 = row0 + 8;
            const u32* yh0 = (const u32*)&s.xc[row0 * XC_S];
            const u32* yh8 = (const u32*)&s.xc[row8 * XC_S];
            float acc[2][4];
#pragma unroll
            for (int nt = 0; nt < 2; nt++)
#pragma unroll
                for (int i = 0; i < 4; i++) acc[nt][i] = 0.0f;
#pragma unroll
            for (int ks = 0; ks < 8; ks++) {
                const int kp = ks * 8 + cc;
                u32 ah[4], al[4];
                ah[0] = yh0[kp];          ah[1] = yh8[kp];
                ah[2] = yh0[kp + 4];      ah[3] = yh8[kp + 4];
                al[0] = yh0[64 + kp];     al[1] = yh8[64 + kp];
                al[2] = yh0[64 + kp + 4]; al[3] = yh8[64 + kp + 4];
                for (int nt = ntb; nt < nte; nt++) {
                    int a = nt - ntb;
                    ull hv = __ldg((const ull*)&gb->xpjPh[((ks * 5 + nt) * 32 + lane) * 2]);
                    ull lv = __ldg((const ull*)&gb->xpjPl[((ks * 5 + nt) * 32 + lane) * 2]);
                    u32 bh0 = (u32)hv, bh1 = (u32)(hv >> 32);
                    u32 bl0 = (u32)lv, bl1 = (u32)(lv >> 32);
                    mma_bf16(acc[a], ah, bh0, bh1);
                    mma_bf16(acc[a], ah, bl0, bl1);
                    mma_bf16(acc[a], al, bh0, bh1);
                }
            }
            for (int nt = ntb; nt < nte; nt++) {
                int a = nt - ntb;
                int col = nt * 8 + 2 * cc;
                *(float2*)&proj[row0 * PROJ_S + col] = make_float2(acc[a][0], acc[a][1]);
                *(float2*)&proj[row8 * PROJ_S + col] = make_float2(acc[a][2], acc[a][3]);
            }
        }
        group_bar(q);

        // ======== stage B: dt/BC/y for rows rb4..rb4+3 ========
        {
            float4 pj[4];
#pragma unroll
            for (int j = 0; j < 4; j++)
                pj[j] = *(const float4*)&proj[(rb4 + j) * PROJ_S];
            float bc[4];
            {
                const int j2 = lane >> 4, sidx = lane & 15;
#pragma unroll
                for (int a = 0; a < 2; a++) {
                    const float* pr = &proj[(rb4 + 2 * a + j2) * PROJ_S];
                    float v = pr[4 + sidx] * pr[20 + sidx];
                    v = half_sum(v);
                    bc[2 * a + 0] = __shfl_sync(0xffffffffu, v, 0);
                    bc[2 * a + 1] = __shfl_sync(0xffffffffu, v, 16);
                }
            }
            float dts[4][4];
            {
                float4 dtbv = __ldg((const float4*)&gb->dtb[4 * lane]);
#pragma unroll
                for (int j = 0; j < 4; j++) {
                    dts[j][0] = dtbv.x; dts[j][1] = dtbv.y;
                    dts[j][2] = dtbv.z; dts[j][3] = dtbv.w;
                }
#pragma unroll
                for (int r = 0; r < 4; r++) {
                    float4 dwv = __ldg((const float4*)&gb->dtw[r * 128 + 4 * lane]);
#pragma unroll
                    for (int j = 0; j < 4; j++) {
                        float prj = fget(pj[j], r);
                        dts[j][0] = fmaf(prj, dwv.x, dts[j][0]);
                        dts[j][1] = fmaf(prj, dwv.y, dts[j][1]);
                        dts[j][2] = fmaf(prj, dwv.z, dts[j][2]);
                        dts[j][3] = fmaf(prj, dwv.w, dts[j][3]);
                    }
                }
#pragma unroll
                for (int j = 0; j < 4; j++) {
                    dts[j][0] = softplusf(dts[j][0]); dts[j][1] = softplusf(dts[j][1]);
                    dts[j][2] = softplusf(dts[j][2]); dts[j][3] = softplusf(dts[j][3]);
                }
            }
            {
                float4 dskv = __ldg((const float4*)&gb->dskip[4 * lane]);
#pragma unroll
                for (int j = 0; j < 4; j++) {
                    u32* xr = (u32*)&s.xc[(rb4 + j) * XC_S];
                    uint2 hh = *(const uint2*)&xr[2 * lane];
                    uint2 ll = *(const uint2*)&xr[64 + 2 * lane];
                    float xc0 = __uint_as_float(hh.x << 16) + __uint_as_float(ll.x << 16);
                    float xc1 = __uint_as_float(hh.x & 0xffff0000u) + __uint_as_float(ll.x & 0xffff0000u);
                    float xc2 = __uint_as_float(hh.y << 16) + __uint_as_float(ll.y << 16);
                    float xc3 = __uint_as_float(hh.y & 0xffff0000u) + __uint_as_float(ll.y & 0xffff0000u);
                    float4 szv = *(const float4*)&s.sz[(rb4 + j) * XC_S + 4 * lane];
                    float4 yv;
                    yv.x = xc0 * fmaf(dts[j][0], bc[j], dskv.x) * szv.x;
                    yv.y = xc1 * fmaf(dts[j][1], bc[j], dskv.y) * szv.y;
                    yv.z = xc2 * fmaf(dts[j][2], bc[j], dskv.z) * szv.z;
                    yv.w = xc3 * fmaf(dts[j][3], bc[j], dskv.w) * szv.w;
                    u32 h0, l0, h1, l1;
                    bfsplit(make_float2(yv.x, yv.y), h0, l0);
                    bfsplit(make_float2(yv.z, yv.w), h1, l1);
                    *(uint2*)&xr[2 * lane]      = make_uint2(h0, h1);
                    *(uint2*)&xr[64 + 2 * lane] = make_uint2(l0, l1);
                }
            }
        }
        group_bar(q);

        // ======== stage C: out-proj GEMM; B via LDG.128 ========
        {
            const int row0 = 16 * q + g, row8 = row0 + 8;
            const u32* yh0 = (const u32*)&s.xc[row0 * XC_S];
            const u32* yh8 = (const u32*)&s.xc[row8 * XC_S];
            float acc[2][4];
#pragma unroll
            for (int nt = 0; nt < 2; nt++)
#pragma unroll
                for (int i = 0; i < 4; i++) acc[nt][i] = 0.0f;
#pragma unroll
            for (int ks = 0; ks < 8; ks++) {
                const int kp = ks * 8 + cc;
                u32 ah[4], al[4];
                ah[0] = yh0[kp];          ah[1] = yh8[kp];
                ah[2] = yh0[kp + 4];      ah[3] = yh8[kp + 4];
                al[0] = yh0[64 + kp];     al[1] = yh8[64 + kp];
                al[2] = yh0[64 + kp + 4]; al[3] = yh8[64 + kp + 4];
                uint4 UH = __ldg((const uint4*)&gb->opwPh[(((ks * 4 + nc) * 32) + lane) * 4]);
                uint4 UL = __ldg((const uint4*)&gb->opwPl[(((ks * 4 + nc) * 32) + lane) * 4]);
                mma_bf16(acc[0], ah, UH.x, UH.z);
                mma_bf16(acc[0], ah, UL.x, UL.z);
                mma_bf16(acc[0], al, UH.x, UH.z);
                mma_bf16(acc[1], ah, UH.y, UH.w);
                mma_bf16(acc[1], ah, UL.y, UL.w);
                mma_bf16(acc[1], al, UH.y, UH.w);
            }
#pragma unroll
            for (int nt = 0; nt < 2; nt++) {
                int col = nc * 16 + nt * 8 + 2 * cc;
                *(float2*)&s.sz[row0 * XC_S + col] = make_float2(acc[nt][0], acc[nt][1]);
                *(float2*)&s.sz[row8 * XC_S + col] = make_float2(acc[nt][2], acc[nt][3]);
            }
        }
        __syncthreads();

        // ======== stage D: layernorm(64) + residual; write fp32 + split ========
        {
            float2 gv = __ldg((const float2*)&gb->lng[2 * lane]);
            float2 bv = __ldg((const float2*)&gb->lnb[2 * lane]);
#pragma unroll
            for (int j = 0; j < 4; j++) {
                int row = rb4 + j;
                float2 ov = *(const float2*)&s.sz[row * XC_S + 2 * lane];
                float m  = warp_sum(ov.x + ov.y) * (1.0f / 64.0f);
                float m2 = warp_sum(ov.x * ov.x + ov.y * ov.y) * (1.0f / 64.0f);
                float rs = rsqrtf(m2 - m * m + EPSV);
                float2 xv = *(const float2*)&s.xs[row * XS_S + 2 * lane];
                xv.x += (ov.x - m) * rs * gv.x + bv.x;
                xv.y += (ov.y - m) * rs * gv.y + bv.y;
                *(float2*)&s.xs[row * XS_S + 2 * lane] = xv;
                u32 h, lo; bfsplit(xv, h, lo);
                s.xsh[row * XH_S + lane] = h;
                s.xsl[row * XH_S + lane] = lo;
            }
        }
    }

    // ================= head =================
    __syncthreads();
    {
        float* hs = s.xc;   // reuse as hw1[128][33]
        for (int i = t; i < 4096; i += THREADS) {
            int k = i >> 5, c = i & 31;
            hs[k * 33 + c] = hw1[i];
        }
        float* hb1s = s.sz;
        float* hw2s = s.sz + 64;
        if (t < 32) { hb1s[t] = hb1[t]; hw2s[t] = hw2[t]; }
        __syncthreads();

        float b2v = hb2[0];
#pragma unroll
        for (int j = 0; j < 2; j++) {
            int ra = 4 * w + 2 * j;
            float h = hb1s[lane];
            const float* xa = &s.xs[ra * XS_S];
            const float* xb = &s.xs[(ra + 1) * XS_S];
#pragma unroll 8
            for (int k = 0; k < 64; k++) h = fmaf(xa[k], hs[k * 33 + lane], h);
#pragma unroll 8
            for (int k = 0; k < 64; k++) h = fmaf(xb[k], hs[(64 + k) * 33 + lane], h);
            h = fmaxf(h, 0.0f);
            float v = warp_sum(h * hw2s[lane]);
            if (lane == 0) out[blockIdx.x * EPB + 2 * w + j] = v + b2v;
        }
    }
}

extern "C" void kernel_launch(void* const* d_in, const int* in_sizes, int n_in,
                              void* d_out, int out_size) {
    const float* x        = (const float*)d_in[0];
    const float* w_nr     = (const float*)d_in[1];
    const float* b_nr     = (const float*)d_in[2];
    const float* w_r      = (const float*)d_in[3];
    const float* b_r      = (const float*)d_in[4];
    const float* w_in_nr  = (const float*)d_in[5];
    const float* b_in_nr  = (const float*)d_in[6];
    const float* w_in_r   = (const float*)d_in[7];
    const float* b_in_r   = (const float*)d_in[8];
    const float* ipw      = (const float*)d_in[9];
    const float* cw       = (const float*)d_in[10];
    const float* cb       = (const float*)d_in[11];
    const float* xpw      = (const float*)d_in[12];
    const float* dtw      = (const float*)d_in[13];
    const float* dtb      = (const float*)d_in[14];
    /* alog d_in[15] dead at L=1 (scan h0=0) */
    const float* dskip    = (const float*)d_in[16];
    const float* opw      = (const float*)d_in[17];
    const float* lng      = (const float*)d_in[18];
    const float* lnb      = (const float*)d_in[19];
    const float* hw1      = (const float*)d_in[20];
    const float* hb1      = (const float*)d_in[21];
    const float* hw2      = (const float*)d_in[22];
    const float* hb2      = (const float*)d_in[23];

    size_t smem = sizeof(Smem);
    cudaFuncSetAttribute((const void*)mamba_main,
                         cudaFuncAttributeMaxDynamicSharedMemorySize, (int)smem);

    prep_all<<<FOLD_BLKS + BLOB_BLKS, 256>>>(w_nr, b_nr, w_r, b_r, w_in_nr, w_in_r,
                                             ipw, opw, xpw, dtw, cw, cb, dtb, dskip,
                                             lng, lnb);
    mamba_main<<<NBLK, THREADS, smem>>>(x, b_in_nr, b_in_r, hw1, hb1, hw2, hb2,
                                        (float*)d_out);
}

// round 17
// speedup vs baseline: 1.1581x; 1.0863x over previous
#include <cuda_runtime.h>

#define NL 4
#define BATCH 16384
#define THREADS 256
#define EPB 16
#define NBLK (BATCH / EPB)       // 1024 blocks, 3 per SM
#define XS_S 68
#define XC_S 132
#define XH_S 36
#define PROJ_S 72
#define NCHUNK 16
#define EPSV 1e-5f

typedef unsigned long long ull;
typedef unsigned int u32;

__device__ __forceinline__ ull pk2(float lo, float hi) {
    ull r; asm("mov.b64 %0,{%1,%2};" : "=l"(r) : "f"(lo), "f"(hi)); return r;
}
__device__ __forceinline__ void upk2(ull v, float& lo, float& hi) {
    asm("mov.b64 {%0,%1},%2;" : "=f"(lo), "=f"(hi) : "l"(v));
}
__device__ __forceinline__ ull ffma2(ull a, ull b, ull c) {
    ull d; asm("fma.rn.f32x2 %0,%1,%2,%3;" : "=l"(d) : "l"(a), "l"(b), "l"(c)); return d;
}
__device__ __forceinline__ float warp_sum(float v) {
    v += __shfl_xor_sync(0xffffffffu, v, 16);
    v += __shfl_xor_sync(0xffffffffu, v, 8);
    v += __shfl_xor_sync(0xffffffffu, v, 4);
    v += __shfl_xor_sync(0xffffffffu, v, 2);
    v += __shfl_xor_sync(0xffffffffu, v, 1);
    return v;
}
__device__ __forceinline__ float half_sum(float v) {
    v += __shfl_xor_sync(0xffffffffu, v, 8);
    v += __shfl_xor_sync(0xffffffffu, v, 4);
    v += __shfl_xor_sync(0xffffffffu, v, 2);
    v += __shfl_xor_sync(0xffffffffu, v, 1);
    return v;
}
__device__ __forceinline__ void group_bar(int q) {
    asm volatile("bar.sync %0, 128;" :: "r"(q + 1) : "memory");
}
// silu via single-MUFU tanh: v*sigmoid(v) = 0.5v(1+tanh(v/2))
__device__ __forceinline__ float siluf(float v) {
    float t;
    asm("tanh.approx.f32 %0, %1;" : "=f"(t) : "f"(0.5f * v));
    return 0.5f * v * (1.0f + t);
}
__device__ __forceinline__ float softplusf(float v) {
    return fmaxf(v, 0.0f) + __logf(1.0f + __expf(-fabsf(v)));
}
__device__ __forceinline__ float fget(float4 v, int r) {
    return r == 0 ? v.x : r == 1 ? v.y : r == 2 ? v.z : v.w;
}
__device__ __forceinline__ u32 uget(uint4 v, int r) {
    return r == 0 ? v.x : r == 1 ? v.y : r == 2 ? v.z : v.w;
}
__device__ __forceinline__ void bfsplit(float2 p, u32& h, u32& l) {
    asm("cvt.rn.satfinite.bf16x2.f32 %0,%1,%2;" : "=r"(h) : "f"(p.y), "f"(p.x));
    float h0 = __uint_as_float(h << 16);
    float h1 = __uint_as_float(h & 0xffff0000u);
    asm("cvt.rn.satfinite.bf16x2.f32 %0,%1,%2;" : "=r"(l) : "f"(p.y - h1), "f"(p.x - h0));
}
__device__ __forceinline__ void mma_bf16(float* c, const u32* a, u32 b0, u32 b1) {
    asm("mma.sync.aligned.m16n8k16.row.col.f32.bf16.bf16.f32 "
        "{%0,%1,%2,%3},{%4,%5,%6,%7},{%8,%9},{%0,%1,%2,%3};"
        : "+f"(c[0]), "+f"(c[1]), "+f"(c[2]), "+f"(c[3])
        : "r"(a[0]), "r"(a[1]), "r"(a[2]), "r"(a[3]), "r"(b0), "r"(b1));
}

// ---------- per-layer weight blob: fragment-order packing (L2-resident, R14) ----------
// ipwP slot s of 16-word group holds chunk c = s^sw; chunk 0: (kp, nt0-3),
// chunk 1: (kp, nt4-7), chunk 2: (kp+4, nt0-3), chunk 3: (kp+4, nt4-7)
struct __align__(16) LayerBlob {
    u32 ipwPh[4 * 4 * 32 * 16];
    u32 ipwPl[4 * 4 * 32 * 16];
    u32 opwPh[8 * 4 * 32 * 4];
    u32 opwPl[8 * 4 * 32 * 4];
    u32 xpjPh[8 * 5 * 32 * 2];
    u32 xpjPl[8 * 5 * 32 * 2];
    float dtw[4 * 128];
    float cw3[128];
    float cb[128];
    float dtb[128];
    float dskip[128];
    float lng[64];
    float lnb[64];
};

__device__ LayerBlob g_blob[NL];
__device__ float g_fold_part[18 * NCHUNK * 64];

#define FOLD_BLKS (18 * NCHUNK)
#define B0 (NL * 8192)
#define B1 (B0 + NL * 4096)
#define B2 (B1 + NL * 2560)
#define B3 (B2 + NL * 512)
#define B4 (B3 + NL * 128)
#define B5 (B4 + NL * 128)
#define B6 (B5 + NL * 128)
#define B7 (B6 + NL * 128)
#define B8 (B7 + NL * 64)
#define B9 (B8 + NL * 64)
#define BLOB_BLKS ((B9 + 255) / 256)

__global__ void __launch_bounds__(256)
prep_all(const float* __restrict__ w_nr, const float* __restrict__ b_nr,
         const float* __restrict__ w_r,  const float* __restrict__ b_r,
         const float* __restrict__ w_in_nr, const float* __restrict__ w_in_r,
         const float* __restrict__ ipw, const float* __restrict__ opw,
         const float* __restrict__ xpw, const float* __restrict__ dtw,
         const float* __restrict__ cw,  const float* __restrict__ cb,
         const float* __restrict__ dtb, const float* __restrict__ dskip,
         const float* __restrict__ lng, const float* __restrict__ lnb) {
    if (blockIdx.x < FOLD_BLKS) {
        __shared__ float red[4][64];
        const int j = blockIdx.x / NCHUNK;
        const int chunk = blockIdx.x - j * NCHUNK;
        const int o = threadIdx.x & 63;
        const int cg = threadIdx.x >> 6;
        const float* vec;
        const float* mat;
        if (j < 12)       { vec = w_nr + j * 1000;        mat = w_in_nr; }
        else if (j == 12) { vec = b_nr;                   mat = w_in_nr; }
        else if (j < 17)  { vec = w_r + (j - 13) * 1000;  mat = w_in_r;  }
        else              { vec = b_r;                    mat = w_in_r;  }
        const int cbase = chunk * 63;
        const int cend = (cbase + 63 < 1000) ? cbase + 63 : 1000;
        float a0 = 0.f, a1 = 0.f;
        for (int c = cbase + cg * 2; c < cend; c += 8) {
            a0 = fmaf(vec[c], mat[c * 64 + o], a0);
            if (c + 1 < cend)
                a1 = fmaf(vec[c + 1], mat[(c + 1) * 64 + o], a1);
        }
        red[cg][o] = a0 + a1;
        __syncthreads();
        if (cg == 0)
            g_fold_part[(j * NCHUNK + chunk) * 64 + o] =
                (red[0][o] + red[1][o]) + (red[2][o] + red[3][o]);
        return;
    }
    int idx = (blockIdx.x - FOLD_BLKS) * 256 + threadIdx.x;
    if (idx < B0) {
        int l = idx >> 13, r = idx & 8191;
        int pos = r & 15, lane = (r >> 4) & 31, t2 = r >> 9;
        int nc = t2 & 3, ks = t2 >> 2;
        int sw = (lane >> 1) & 3;
        int c = (pos >> 2) ^ sw;
        int jw = pos & 3;
        int g = lane >> 2, cc = lane & 3;
        int kp = ks * 8 + cc + ((c >= 2) ? 4 : 0);
        int nt = (c & 1) * 4 + jw;
        int n = nc * 64 + nt * 8 + g;
        const float* src = ipw + l * 16384 + kp * 512 + n;
        u32 h, lo; bfsplit(make_float2(src[0], src[256]), h, lo);
        g_blob[l].ipwPh[r] = h;
        g_blob[l].ipwPl[r] = lo;
    } else if (idx < B1) {
        int j2 = idx - B0, l = j2 >> 12, r = j2 & 4095;
        int jw = r & 3, lane = (r >> 2) & 31, t2 = r >> 7;
        int nc = t2 & 3, ks = t2 >> 2;
        int g = lane >> 2, cc = lane & 3;
        int kp = ks * 8 + cc + ((jw >= 2) ? 4 : 0);
        int nt = jw & 1;
        int n = nc * 16 + nt * 8 + g;
        const float* src = opw + l * 8192 + kp * 128 + n;
        u32 h, lo; bfsplit(make_float2(src[0], src[64]), h, lo);
        g_blob[l].opwPh[r] = h;
        g_blob[l].opwPl[r] = lo;
    } else if (idx < B2) {
        int j2 = idx - B1, l = j2 / 2560, r = j2 - l * 2560;
        int e = r & 1, lane = (r >> 1) & 31, t2 = r >> 6;
        int nt = t2 % 5, ks = t2 / 5;
        int g = lane >> 2, cc = lane & 3;
        int kp = ks * 8 + cc + (e ? 4 : 0);
        int n = nt * 8 + g;
        const float* src = xpw + l * 4608 + (2 * kp) * 36 + n;
        u32 h, lo; bfsplit(make_float2(src[0], src[36]), h, lo);
        g_blob[l].xpjPh[r] = h;
        g_blob[l].xpjPl[r] = lo;
    } else if (idx < B3) {
        int j = idx - B2, l = j >> 9, r = j & 511;
        g_blob[l].dtw[r] = dtw[l * 512 + r];
    } else if (idx < B4) {
        int j = idx - B3, l = j >> 7, r = j & 127;
        g_blob[l].cw3[r] = cw[(l * 128 + r) * 4 + 3];
    } else if (idx < B5) {
        int j = idx - B4, l = j >> 7, r = j & 127;
        g_blob[l].cb[r] = cb[l * 128 + r];
    } else if (idx < B6) {
        int j = idx - B5, l = j >> 7, r = j & 127;
        g_blob[l].dtb[r] = dtb[l * 128 + r];
    } else if (idx < B7) {
        int j = idx - B6, l = j >> 7, r = j & 127;
        g_blob[l].dskip[r] = dskip[l * 128 + r];
    } else if (idx < B8) {
        int j = idx - B7, l = j >> 6, r = j & 63;
        g_blob[l].lng[r] = lng[l * 64 + r];
    } else if (idx < B9) {
        int j = idx - B8, l = j >> 6, r = j & 63;
        g_blob[l].lnb[r] = lnb[l * 64 + r];
    }
}

// ---------------- shared memory (51,712 B; 3 blocks/SM) ----------------
struct __align__(16) Smem {
    u32 xsh[32 * XH_S];
    u32 xsl[32 * XH_S];
    float xs[32 * XS_S];
    float xc[32 * XC_S];
    float sz[32 * XC_S];
};

__global__ void __launch_bounds__(THREADS, 3)
mamba_main(const float* __restrict__ xin,
           const float* __restrict__ b_in_nr, const float* __restrict__ b_in_r,
           const float* __restrict__ hw1, const float* __restrict__ hb1,
           const float* __restrict__ hw2, const float* __restrict__ hb2,
           float* __restrict__ out) {
    extern __shared__ __align__(16) char smem_raw[];
    Smem& s = *reinterpret_cast<Smem*>(smem_raw);

    const int t = threadIdx.x;
    const int w = t >> 5;          // 0..7
    const int lane = t & 31;
    const int q = w & 1;
    const int nc = w >> 1;
    const int g = lane >> 2;
    const int cc = lane & 3;
    const int sw = (lane >> 1) & 3;
    const int rb4 = 16 * q + 4 * nc;
    float* proj = (float*)s.xsh;

    // ---- fold-reduce into SMEM (union'd into xc region) ----
    float* Wnr_s = s.xc;
    float* Wr_s  = s.xc + 768;
    float* bnr_s = s.xc + 1024;
    float* br_s  = s.xc + 1088;
    for (int i = t; i < 1152; i += THREADS) {
        int j = i >> 6, o = i & 63;
        const float* p = g_fold_part + (j * NCHUNK) * 64 + o;
        float a = 0.0f;
#pragma unroll
        for (int k = 0; k < NCHUNK; k++) a += p[k * 64];
        if (j < 12)       Wnr_s[j * 64 + o] = a;
        else if (j == 12) bnr_s[o] = a + b_in_nr[o];
        else if (j < 17)  Wr_s[(j - 13) * 64 + o] = a;
        else              br_s[o] = a + b_in_r[o];
    }
    __syncthreads();

    // ---- x0 = feat @ W_eff + b_eff : warp w -> rows 4w..4w+3 ----
    {
        const int e0 = blockIdx.x * EPB + 2 * w;
        float fe[2][16];
#pragma unroll
        for (int e = 0; e < 2; e++) {
            const float4* xp = (const float4*)(xin + (size_t)(e0 + e) * 16);
#pragma unroll
            for (int qq = 0; qq < 4; qq++) {
                float4 v = xp[qq];
                fe[e][4 * qq + 0] = v.x; fe[e][4 * qq + 1] = v.y;
                fe[e][4 * qq + 2] = v.z; fe[e][4 * qq + 3] = v.w;
            }
        }
        float2 bn = *(const float2*)&bnr_s[2 * lane];
        float2 bb = *(const float2*)&br_s[2 * lane];
        ull a0 = pk2(bn.x, bn.y), a2 = a0;
        ull a1 = pk2(bb.x, bb.y), a3 = a1;
#pragma unroll
        for (int f = 0; f < 12; f++) {
            ull wp = *(const ull*)&Wnr_s[f * 64 + 2 * lane];
            a0 = ffma2(wp, pk2(fe[0][f], fe[0][f]), a0);
            a2 = ffma2(wp, pk2(fe[1][f], fe[1][f]), a2);
        }
#pragma unroll
        for (int f = 0; f < 4; f++) {
            ull wp = *(const ull*)&Wr_s[f * 64 + 2 * lane];
            a1 = ffma2(wp, pk2(fe[0][12 + f], fe[0][12 + f]), a1);
            a3 = ffma2(wp, pk2(fe[1][12 + f], fe[1][12 + f]), a3);
        }
        ull accs[4] = {a0, a1, a2, a3};
#pragma unroll
        for (int j = 0; j < 4; j++) {
            float v0, v1; upk2(accs[j], v0, v1);
            int row = 4 * w + j;
            *(float2*)&s.xs[row * XS_S + 2 * lane] = make_float2(v0, v1);
            u32 h, lo; bfsplit(make_float2(v0, v1), h, lo);
            s.xsh[row * XH_S + lane] = h;
            s.xsl[row * XH_S + lane] = lo;
        }
    }

    // ================= layer loop (weights served from L2) =================
#pragma unroll 1
    for (int l = 0; l < NL; l++) {
        const LayerBlob* __restrict__ gb = &g_blob[l];
        __syncthreads();

        // ======== stage A: xz GEMM in two nt-halves (register diet) ========
        {
            const int row0 = 16 * q + g, row8 = row0 + 8;
            const u32* xh0 = &s.xsh[row0 * XH_S];
            const u32* xh8 = &s.xsh[row8 * XH_S];
            const u32* xl0 = &s.xsl[row0 * XH_S];
            const u32* xl8 = &s.xsl[row8 * XH_S];
#pragma unroll
            for (int half = 0; half < 2; half++) {
                float acc[4][4];
#pragma unroll
                for (int nt = 0; nt < 4; nt++)
#pragma unroll
                    for (int i = 0; i < 4; i++) acc[nt][i] = 0.0f;
#pragma unroll
                for (int ks = 0; ks < 4; ks++) {
                    const int kp = ks * 8 + cc;
                    u32 ah[4], al[4];
                    ah[0] = xh0[kp];     ah[1] = xh8[kp];
                    ah[2] = xh0[kp + 4]; ah[3] = xh8[kp + 4];
                    al[0] = xl0[kp];     al[1] = xl8[kp];
                    al[2] = xl0[kp + 4]; al[3] = xl8[kp + 4];
                    const uint4* bp_h = (const uint4*)&gb->ipwPh[(((ks * 4 + nc) * 32) + lane) * 16];
                    const uint4* bp_l = (const uint4*)&gb->ipwPl[(((ks * 4 + nc) * 32) + lane) * 16];
                    // chunk (half) = b0 words, chunk (half+2) = b1 words
                    uint4 C0 = __ldg(&bp_h[half ^ sw]);
                    uint4 C1 = __ldg(&bp_h[(half + 2) ^ sw]);
                    uint4 D0 = __ldg(&bp_l[half ^ sw]);
                    uint4 D1 = __ldg(&bp_l[(half + 2) ^ sw]);
#pragma unroll
                    for (int nt = 0; nt < 4; nt++) {
                        u32 b0 = uget(C0, nt), b1 = uget(C1, nt);
                        mma_bf16(acc[nt], ah, b0, b1);
                        mma_bf16(acc[nt], al, b0, b1);
                        u32 e0w = uget(D0, nt), e1w = uget(D1, nt);
                        mma_bf16(acc[nt], ah, e0w, e1w);
                    }
                }
                if (nc < 2) {    // xc half: conv tap + silu, stored split
                    u32* xr0 = (u32*)&s.xc[row0 * XC_S];
                    u32* xr8 = (u32*)&s.xc[row8 * XC_S];
#pragma unroll
                    for (int nt = 0; nt < 4; nt++) {
                        int col = nc * 64 + (half * 4 + nt) * 8 + 2 * cc;
                        int p = col >> 1;
                        float2 cwv = *(const float2*)&gb->cw3[col];
                        float2 cbv = *(const float2*)&gb->cb[col];
                        float2 v0 = make_float2(siluf(fmaf(acc[nt][0], cwv.x, cbv.x)),
                                                siluf(fmaf(acc[nt][1], cwv.y, cbv.y)));
                        float2 v8 = make_float2(siluf(fmaf(acc[nt][2], cwv.x, cbv.x)),
                                                siluf(fmaf(acc[nt][3], cwv.y, cbv.y)));
                        u32 h, lo;
                        bfsplit(v0, h, lo); xr0[p] = h; xr0[64 + p] = lo;
                        bfsplit(v8, h, lo); xr8[p] = h; xr8[64 + p] = lo;
                    }
                } else {         // z half: silu, fp32
#pragma unroll
                    for (int nt = 0; nt < 4; nt++) {
                        int col = (nc - 2) * 64 + (half * 4 + nt) * 8 + 2 * cc;
                        *(float2*)&s.sz[row0 * XC_S + col] =
                            make_float2(siluf(acc[nt][0]), siluf(acc[nt][1]));
                        *(float2*)&s.sz[row8 * XC_S + col] =
                            make_float2(siluf(acc[nt][2]), siluf(acc[nt][3]));
                    }
                }
            }
        }
        __syncthreads();

        // ======== proj GEMM: n-tiles 2/1/1/1; B via LDG.64 ========
        {
            const int ntb = (nc == 0) ? 0 : nc + 1;
            const int nte = nc + 2;
            const int row0 = 16 * q + g, row8 = row0 + 8;
            const u32* yh0 = (const u32*)&s.xc[row0 * XC_S];
            const u32* yh8 = (const u32*)&s.xc[row8 * XC_S];
            float acc[2][4];
#pragma unroll
            for (int nt = 0; nt < 2; nt++)
#pragma unroll
                for (int i = 0; i < 4; i++) acc[nt][i] = 0.0f;
#pragma unroll
            for (int ks = 0; ks < 8; ks++) {
                const int kp = ks * 8 + cc;
                u32 ah[4], al[4];
                ah[0] = yh0[kp];          ah[1] = yh8[kp];
                ah[2] = yh0[kp + 4];      ah[3] = yh8[kp + 4];
                al[0] = yh0[64 + kp];     al[1] = yh8[64 + kp];
                al[2] = yh0[64 + kp + 4]; al[3] = yh8[64 + kp + 4];
                for (int nt = ntb; nt < nte; nt++) {
                    int a = nt - ntb;
                    ull hv = __ldg((const ull*)&gb->xpjPh[((ks * 5 + nt) * 32 + lane) * 2]);
                    ull lv = __ldg((const ull*)&gb->xpjPl[((ks * 5 + nt) * 32 + lane) * 2]);
                    u32 bh0 = (u32)hv, bh1 = (u32)(hv >> 32);
                    u32 bl0 = (u32)lv, bl1 = (u32)(lv >> 32);
                    mma_bf16(acc[a], ah, bh0, bh1);
                    mma_bf16(acc[a], ah, bl0, bl1);
                    mma_bf16(acc[a], al, bh0, bh1);
                }
            }
            for (int nt = ntb; nt < nte; nt++) {
                int a = nt - ntb;
                int col = nt * 8 + 2 * cc;
                *(float2*)&proj[row0 * PROJ_S + col] = make_float2(acc[a][0], acc[a][1]);
                *(float2*)&proj[row8 * PROJ_S + col] = make_float2(acc[a][2], acc[a][3]);
            }
        }
        group_bar(q);

        // ======== stage B: dt/BC/y for rows rb4..rb4+3 ========
        {
            float4 pj[4];
#pragma unroll
            for (int j = 0; j < 4; j++)
                pj[j] = *(const float4*)&proj[(rb4 + j) * PROJ_S];
            float bc[4];
            {
                const int j2 = lane >> 4, sidx = lane & 15;
#pragma unroll
                for (int a = 0; a < 2; a++) {
                    const float* pr = &proj[(rb4 + 2 * a + j2) * PROJ_S];
                    float v = pr[4 + sidx] * pr[20 + sidx];
                    v = half_sum(v);
                    bc[2 * a + 0] = __shfl_sync(0xffffffffu, v, 0);
                    bc[2 * a + 1] = __shfl_sync(0xffffffffu, v, 16);
                }
            }
            float dts[4][4];
            {
                float4 dtbv = __ldg((const float4*)&gb->dtb[4 * lane]);
#pragma unroll
                for (int j = 0; j < 4; j++) {
                    dts[j][0] = dtbv.x; dts[j][1] = dtbv.y;
                    dts[j][2] = dtbv.z; dts[j][3] = dtbv.w;
                }
#pragma unroll
                for (int r = 0; r < 4; r++) {
                    float4 dwv = __ldg((const float4*)&gb->dtw[r * 128 + 4 * lane]);
#pragma unroll
                    for (int j = 0; j < 4; j++) {
                        float prj = fget(pj[j], r);
                        dts[j][0] = fmaf(prj, dwv.x, dts[j][0]);
                        dts[j][1] = fmaf(prj, dwv.y, dts[j][1]);
                        dts[j][2] = fmaf(prj, dwv.z, dts[j][2]);
                        dts[j][3] = fmaf(prj, dwv.w, dts[j][3]);
                    }
                }
#pragma unroll
                for (int j = 0; j < 4; j++) {
                    dts[j][0] = softplusf(dts[j][0]); dts[j][1] = softplusf(dts[j][1]);
                    dts[j][2] = softplusf(dts[j][2]); dts[j][3] = softplusf(dts[j][3]);
                }
            }
            {
                float4 dskv = __ldg((const float4*)&gb->dskip[4 * lane]);
#pragma unroll
                for (int j = 0; j < 4; j++) {
                    u32* xr = (u32*)&s.xc[(rb4 + j) * XC_S];
                    uint2 hh = *(const uint2*)&xr[2 * lane];
                    uint2 ll = *(const uint2*)&xr[64 + 2 * lane];
                    float xc0 = __uint_as_float(hh.x << 16) + __uint_as_float(ll.x << 16);
                    float xc1 = __uint_as_float(hh.x & 0xffff0000u) + __uint_as_float(ll.x & 0xffff0000u);
                    float xc2 = __uint_as_float(hh.y << 16) + __uint_as_float(ll.y << 16);
                    float xc3 = __uint_as_float(hh.y & 0xffff0000u) + __uint_as_float(ll.y & 0xffff0000u);
                    float4 szv = *(const float4*)&s.sz[(rb4 + j) * XC_S + 4 * lane];
                    float4 yv;
                    yv.x = xc0 * fmaf(dts[j][0], bc[j], dskv.x) * szv.x;
                    yv.y = xc1 * fmaf(dts[j][1], bc[j], dskv.y) * szv.y;
                    yv.z = xc2 * fmaf(dts[j][2], bc[j], dskv.z) * szv.z;
                    yv.w = xc3 * fmaf(dts[j][3], bc[j], dskv.w) * szv.w;
                    u32 h0, l0, h1, l1;
                    bfsplit(make_float2(yv.x, yv.y), h0, l0);
                    bfsplit(make_float2(yv.z, yv.w), h1, l1);
                    *(uint2*)&xr[2 * lane]      = make_uint2(h0, h1);
                    *(uint2*)&xr[64 + 2 * lane] = make_uint2(l0, l1);
                }
            }
        }
        group_bar(q);

        // ======== stage C: out-proj GEMM; B via LDG.128 ========
        {
            const int row0 = 16 * q + g, row8 = row0 + 8;
            const u32* yh0 = (const u32*)&s.xc[row0 * XC_S];
            const u32* yh8 = (const u32*)&s.xc[row8 * XC_S];
            float acc[2][4];
#pragma unroll
            for (int nt = 0; nt < 2; nt++)
#pragma unroll
                for (int i = 0; i < 4; i++) acc[nt][i] = 0.0f;
#pragma unroll
            for (int ks = 0; ks < 8; ks++) {
                const int kp = ks * 8 + cc;
                u32 ah[4], al[4];
                ah[0] = yh0[kp];          ah[1] = yh8[kp];
                ah[2] = yh0[kp + 4];      ah[3] = yh8[kp + 4];
                al[0] = yh0[64 + kp];     al[1] = yh8[64 + kp];
                al[2] = yh0[64 + kp + 4]; al[3] = yh8[64 + kp + 4];
                uint4 UH = __ldg((const uint4*)&gb->opwPh[(((ks * 4 + nc) * 32) + lane) * 4]);
                uint4 UL = __ldg((const uint4*)&gb->opwPl[(((ks * 4 + nc) * 32) + lane) * 4]);
                mma_bf16(acc[0], ah, UH.x, UH.z);
                mma_bf16(acc[0], ah, UL.x, UL.z);
                mma_bf16(acc[0], al, UH.x, UH.z);
                mma_bf16(acc[1], ah, UH.y, UH.w);
                mma_bf16(acc[1], ah, UL.y, UL.w);
                mma_bf16(acc[1], al, UH.y, UH.w);
            }
#pragma unroll
            for (int nt = 0; nt < 2; nt++) {
                int col = nc * 16 + nt * 8 + 2 * cc;
                *(float2*)&s.sz[row0 * XC_S + col] = make_float2(acc[nt][0], acc[nt][1]);
                *(float2*)&s.sz[row8 * XC_S + col] = make_float2(acc[nt][2], acc[nt][3]);
            }
        }
        __syncthreads();

        // ======== stage D: layernorm(64) + residual; write fp32 + split ========
        {
            float2 gv = __ldg((const float2*)&gb->lng[2 * lane]);
            float2 bv = __ldg((const float2*)&gb->lnb[2 * lane]);
#pragma unroll
            for (int j = 0; j < 4; j++) {
                int row = rb4 + j;
                float2 ov = *(const float2*)&s.sz[row * XC_S + 2 * lane];
                float m  = warp_sum(ov.x + ov.y) * (1.0f / 64.0f);
                float m2 = warp_sum(ov.x * ov.x + ov.y * ov.y) * (1.0f / 64.0f);
                float rs = rsqrtf(m2 - m * m + EPSV);
                float2 xv = *(const float2*)&s.xs[row * XS_S + 2 * lane];
                xv.x += (ov.x - m) * rs * gv.x + bv.x;
                xv.y += (ov.y - m) * rs * gv.y + bv.y;
                *(float2*)&s.xs[row * XS_S + 2 * lane] = xv;
                u32 h, lo; bfsplit(xv, h, lo);
                s.xsh[row * XH_S + lane] = h;
                s.xsl[row * XH_S + lane] = lo;
            }
        }
    }

    // ================= head =================
    __syncthreads();
    {
        float* hs = s.xc;   // reuse as hw1[128][33]
        for (int i = t; i < 4096; i += THREADS) {
            int k = i >> 5, c = i & 31;
            hs[k * 33 + c] = hw1[i];
        }
        float* hb1s = s.sz;
        float* hw2s = s.sz + 64;
        if (t < 32) { hb1s[t] = hb1[t]; hw2s[t] = hw2[t]; }
        __syncthreads();

        float b2v = hb2[0];
#pragma unroll
        for (int j = 0; j < 2; j++) {
            int ra = 4 * w + 2 * j;
            float h = hb1s[lane];
            const float* xa = &s.xs[ra * XS_S];
            const float* xb = &s.xs[(ra + 1) * XS_S];
#pragma unroll 8
            for (int k = 0; k < 64; k++) h = fmaf(xa[k], hs[k * 33 + lane], h);
#pragma unroll 8
            for (int k = 0; k < 64; k++) h = fmaf(xb[k], hs[(64 + k) * 33 + lane], h);
            h = fmaxf(h, 0.0f);
            float v = warp_sum(h * hw2s[lane]);
            if (lane == 0) out[blockIdx.x * EPB + 2 * w + j] = v + b2v;
        }
    }
}

extern "C" void kernel_launch(void* const* d_in, const int* in_sizes, int n_in,
                              void* d_out, int out_size) {
    const float* x        = (const float*)d_in[0];
    const float* w_nr     = (const float*)d_in[1];
    const float* b_nr     = (const float*)d_in[2];
    const float* w_r      = (const float*)d_in[3];
    const float* b_r      = (const float*)d_in[4];
    const float* w_in_nr  = (const float*)d_in[5];
    const float* b_in_nr  = (const float*)d_in[6];
    const float* w_in_r   = (const float*)d_in[7];
    const float* b_in_r   = (const float*)d_in[8];
    const float* ipw      = (const float*)d_in[9];
    const float* cw       = (const float*)d_in[10];
    const float* cb       = (const float*)d_in[11];
    const float* xpw      = (const float*)d_in[12];
    const float* dtw      = (const float*)d_in[13];
    const float* dtb      = (const float*)d_in[14];
    /* alog d_in[15] dead at L=1 (scan h0=0) */
    const float* dskip    = (const float*)d_in[16];
    const float* opw      = (const float*)d_in[17];
    const float* lng      = (const float*)d_in[18];
    const float* lnb      = (const float*)d_in[19];
    const float* hw1      = (const float*)d_in[20];
    const float* hb1      = (const float*)d_in[21];
    const float* hw2      = (const float*)d_in[22];
    const float* hb2      = (const float*)d_in[23];

    size_t smem = sizeof(Smem);
    cudaFuncSetAttribute((const void*)mamba_main,
                         cudaFuncAttributeMaxDynamicSharedMemorySize, (int)smem);

    prep_all<<<FOLD_BLKS + BLOB_BLKS, 256>>>(w_nr, b_nr, w_r, b_r, w_in_nr, w_in_r,
                                             ipw, opw, xpw, dtw, cw, cb, dtb, dskip,
                                             lng, lnb);
    mamba_main<<<NBLK, THREADS, smem>>>(x, b_in_nr, b_in_r, hw1, hb1, hw2, hb2,
                                        (float*)d_out);
}